// round 16
// baseline (speedup 1.0000x reference)
#include <cuda_runtime.h>

#define NCTA   8
#define NT     256
#define NWARP  8
#define RPT    4                 // rows per thread: 8*256*4 = 8192
#define NITER  200
#define LROWS  8192

typedef unsigned long long u64;

// err = 2^(-2*bits), bits = {2,3,4,5,6,8,10,12}
__constant__ float c_err[8] = {
    6.25e-2f, 1.5625e-2f, 3.90625e-3f, 9.765625e-4f,
    2.44140625e-4f, 1.52587890625e-5f, 9.5367431640625e-7f, 5.9604644775390625e-8f
};

__device__ float g_sum_n;
__device__ float g_inv_sens;

__device__ __forceinline__ float ex2f(float x) {
    float y; asm("ex2.approx.f32 %0, %1;" : "=f"(y) : "f"(x)); return y;
}
__device__ __forceinline__ float lg2f(float x) {
    float y; asm("lg2.approx.f32 %0, %1;" : "=f"(y) : "f"(x)); return y;
}
__device__ __forceinline__ float rcpf(float x) {
    float y; asm("rcp.approx.f32 %0, %1;" : "=f"(y) : "f"(x)); return y;
}
__device__ __forceinline__ u64 pack2(float lo, float hi) {
    u64 r; asm("mov.b64 %0, {%1, %2};" : "=l"(r) : "f"(lo), "f"(hi)); return r;
}
__device__ __forceinline__ void unpack2(float& lo, float& hi, u64 v) {
    asm("mov.b64 {%0, %1}, %2;" : "=f"(lo), "=f"(hi) : "l"(v));
}
__device__ __forceinline__ u64 fma2(u64 a, u64 b, u64 c) {
    u64 d; asm("fma.rn.f32x2 %0, %1, %2, %3;" : "=l"(d) : "l"(a), "l"(b), "l"(c));
    return d;
}
__device__ __forceinline__ u64 mul2(u64 a, u64 b) {
    u64 d; asm("mul.rn.f32x2 %0, %1, %2;" : "=l"(d) : "l"(a), "l"(b));
    return d;
}
__device__ __forceinline__ unsigned smem_u32(const void* p) {
    unsigned a;
    asm("{ .reg .u64 t; cvta.to.shared.u64 t, %1; cvt.u32.u64 %0, t; }"
        : "=r"(a) : "l"(p));
    return a;
}
__device__ __forceinline__ unsigned mapa_u32(unsigned laddr, unsigned rank) {
    unsigned r;
    asm("mapa.shared::cluster.u32 %0, %1, %2;" : "=r"(r) : "r"(laddr), "r"(rank));
    return r;
}
// remote store whose completion is delivered as a tx-decrement on the target's
// mbarrier -- single cross-SM flight, no separate arrive, no release stall
__device__ __forceinline__ void st_async_b64(unsigned addr, u64 v, unsigned mbar) {
    asm volatile("st.async.shared::cluster.mbarrier::complete_tx::bytes.b64 [%0], %1, [%2];"
                 :: "r"(addr), "l"(v), "r"(mbar) : "memory");
}
__device__ __forceinline__ void mbar_expect_tx(unsigned addr, unsigned bytes) {
    asm volatile("mbarrier.arrive.expect_tx.shared.b64 _, [%0], %1;"
                 :: "r"(addr), "r"(bytes) : "memory");
}
__device__ __forceinline__ void mbar_wait_parity(unsigned addr, unsigned par) {
    asm volatile(
        "{\n\t"
        ".reg .pred P;\n"
        "W%=:\n\t"
        "mbarrier.try_wait.parity.acquire.cta.shared::cta.b64 P, [%0], %1, 0x989680;\n\t"
        "@P bra D%=;\n\t"
        "bra W%=;\n"
        "D%=:\n\t"
        "}"
        :: "r"(addr), "r"(par) : "memory");
}

// ---------------------------------------------------------------------------
// Pre-kernel: global input sums (graph-replay deterministic)
// ---------------------------------------------------------------------------
__global__ void da_pre_kernel(const float* __restrict__ n_raw,
                              const float* __restrict__ sens_raw) {
    __shared__ float s1[8], s2[8];
    int t = threadIdx.x;
    float sn = 0.f, ss = 0.f;
    for (int i = t; i < LROWS; i += 256) { sn += n_raw[i]; ss += sens_raw[i]; }
#pragma unroll
    for (int o = 16; o; o >>= 1) {
        sn += __shfl_xor_sync(0xffffffffu, sn, o);
        ss += __shfl_xor_sync(0xffffffffu, ss, o);
    }
    if ((t & 31) == 0) { s1[t >> 5] = sn; s2[t >> 5] = ss; }
    __syncthreads();
    if (t == 0) {
        float a = 0.f, b = 0.f;
#pragma unroll
        for (int w = 0; w < 8; w++) { a += s1[w]; b += s2[w]; }
        g_sum_n    = a * 1e5f + 1e3f * (float)LROWS;
        g_inv_sens = 1.0f / (b + 1e-12f);
    }
}

// ---------------------------------------------------------------------------
// Main kernel: cluster of 8 CTAs x 256 threads, 4 rows/thread. EXACT recurrence.
// Factorized plan p = p0 * R_i * D_j; d_j = b_j / T_j (rcp.approx).
// FLAT exchange: every warp st.asyncs its 8-col strip (32B) to all 8 CTAs as
// soon as its butterfly finishes; each CTA's mbarrier counts 2048 tx bytes
// (64 warp strips). No sred, no named barrier, no warp-0 aggregation stage.
// ---------------------------------------------------------------------------
__global__ void __launch_bounds__(NT, 1) __cluster_dims__(NCTA, 1, 1)
da_main_kernel(const float* __restrict__ theta,
               const float* __restrict__ phi,
               const float* __restrict__ sens_raw,
               const float* __restrict__ n_raw,
               float* __restrict__ out) {
    __shared__ __align__(16) float recv[2][512];      // [slot][gw*8 + col]
    __shared__ __align__(8) u64 mbar[2];

    const int tid  = threadIdx.x;
    const int lane = tid & 31;
    const int warp = tid >> 5;
    const unsigned FULL = 0xffffffffu;
    const float L2E = 1.4426950408889634f;

    unsigned rank;
    asm("mov.u32 %0, %%cluster_ctarank;" : "=r"(rank));
    const int gw = (int)rank * NWARP + warp;          // global warp id 0..63

    const unsigned recv_base = smem_u32(&recv[0][0]);
    const unsigned mb_addr0  = smem_u32(&mbar[0]);
    const unsigned mb_addr1  = smem_u32(&mbar[1]);

    if (tid == 0) {
        asm volatile("mbarrier.init.shared.b64 [%0], %1;"
                     :: "r"(mb_addr0), "r"(1u) : "memory");
        asm volatile("mbarrier.init.shared.b64 [%0], %1;"
                     :: "r"(mb_addr1), "r"(1u) : "memory");
    }
    asm volatile("barrier.cluster.arrive.aligned;" ::: "memory");
    asm volatile("barrier.cluster.wait.aligned;" ::: "memory");

    // publish addresses: lane t (t<8) -> target CTA (t+rank)&7, strip at gw*32B
    unsigned rem_data = 0, rem_mb0 = 0, rem_mb1 = 0;
    if (lane < 8) {
        unsigned tgt = ((unsigned)lane + rank) & (NCTA - 1);
        rem_data = mapa_u32(recv_base + (unsigned)gw * 32u, tgt);
        rem_mb0  = mapa_u32(mb_addr0, tgt);
        rem_mb1  = mapa_u32(mb_addr1, tgt);
    }

    // b_j (softmax of phi) for column class c = lane&7
    const int mycol = lane & 7;
    float bb_c;
    {
        float q[8];
#pragma unroll
        for (int j = 0; j < 8; j++) q[j] = phi[j] * L2E;
        float m = fmaxf(fmaxf(fmaxf(q[0], q[1]), fmaxf(q[2], q[3])),
                        fmaxf(fmaxf(q[4], q[5]), fmaxf(q[6], q[7])));
        float s = 0.f;
#pragma unroll
        for (int j = 0; j < 8; j++) s += ex2f(q[j] - m);
        bb_c = ex2f(q[mycol] - m - lg2f(s));
    }

    // per-row constants + p0 (packed row-shifted exponentials) + R = a/S
    const int   base = ((int)rank * NT + tid) * RPT;
    const float inv_sumn = 1.0f / g_sum_n;
    const float inv_sens = g_inv_sens;
    const float SC = 50.0f * L2E;

    float a[RPT], R[RPT];
    u64   pp[RPT][4];                       // packed col pairs (01,23,45,67)
    {
        float4 nv = *(const float4*)(n_raw + base);
        float4 sv = *(const float4*)(sens_raw + base);
        float nn[RPT] = { nv.x, nv.y, nv.z, nv.w };
        float se[RPT] = { sv.x, sv.y, sv.z, sv.w };
        const float4* t4 = (const float4*)theta;
#pragma unroll
        for (int e = 0; e < RPT; e++) {
            float n  = nn[e] * 1e5f + 1e3f;
            a[e]     = n * inv_sumn;
            float cs = n * se[e] * inv_sens;
            int   r  = base + e;
            float4 ta = t4[r * 2], tb = t4[r * 2 + 1];
            float x[8];
            x[0] = (ta.x - cs * c_err[0]) * SC;
            x[1] = (ta.y - cs * c_err[1]) * SC;
            x[2] = (ta.z - cs * c_err[2]) * SC;
            x[3] = (ta.w - cs * c_err[3]) * SC;
            x[4] = (tb.x - cs * c_err[4]) * SC;
            x[5] = (tb.y - cs * c_err[5]) * SC;
            x[6] = (tb.z - cs * c_err[6]) * SC;
            x[7] = (tb.w - cs * c_err[7]) * SC;
            float m = fmaxf(fmaxf(fmaxf(x[0], x[1]), fmaxf(x[2], x[3])),
                            fmaxf(fmaxf(x[4], x[5]), fmaxf(x[6], x[7])));
            float p0[8], S = 0.f;
#pragma unroll
            for (int j = 0; j < 8; j++) { p0[j] = ex2f(x[j] - m); S += p0[j]; }
            R[e] = __fdividef(a[e], S);              // rows of p0*R sum to a
#pragma unroll
            for (int q = 0; q < 4; q++) pp[e][q] = pack2(p0[2*q], p0[2*q+1]);
        }
    }

    u64   Dq[4];
#pragma unroll
    for (int q = 0; q < 4; q++) Dq[q] = pack2(1.f, 1.f);
    float Dc = 1.f, Tc = 1.f, dc = 1.f;

    for (int it = 0; it < NITER; ++it) {
        const int      slot = it & 1;
        const unsigned mb_l = slot ? mb_addr1 : mb_addr0;
        const unsigned mb_r = slot ? rem_mb1 : rem_mb0;

        // ---- re-arm local mbar for this iteration (negative tx transients OK)
        if (tid == 0) mbar_expect_tx(mb_l, 64u * 32u);

        // ---- column partials of p0*R over this thread's 4 rows (packed FMA)
        u64 Rp[RPT];
#pragma unroll
        for (int e = 0; e < RPT; e++) Rp[e] = pack2(R[e], R[e]);
        float c0[8];
#pragma unroll
        for (int q = 0; q < 4; q++) {
            u64 acc = mul2(pp[0][q], Rp[0]);
            acc = fma2(pp[1][q], Rp[1], acc);
            acc = fma2(pp[2][q], Rp[2], acc);
            acc = fma2(pp[3][q], Rp[3], acc);
            unpack2(c0[2*q], c0[2*q+1], acc);
        }

        // ---- butterfly transpose-reduce: lane holds warp col sum for col lane&7
        float z;
        {
            float s0 = __shfl_xor_sync(FULL, c0[0], 4);
            float s1 = __shfl_xor_sync(FULL, c0[1], 4);
            float s2 = __shfl_xor_sync(FULL, c0[2], 4);
            float s3 = __shfl_xor_sync(FULL, c0[3], 4);
            float s4 = __shfl_xor_sync(FULL, c0[4], 4);
            float s5 = __shfl_xor_sync(FULL, c0[5], 4);
            float s6 = __shfl_xor_sync(FULL, c0[6], 4);
            float s7 = __shfl_xor_sync(FULL, c0[7], 4);
            bool hi4 = (lane & 4) != 0;
            float u0 = hi4 ? (c0[4] + s4) : (c0[0] + s0);
            float u1 = hi4 ? (c0[5] + s5) : (c0[1] + s1);
            float u2 = hi4 ? (c0[6] + s6) : (c0[2] + s2);
            float u3 = hi4 ? (c0[7] + s7) : (c0[3] + s3);
            float r0 = __shfl_xor_sync(FULL, u0, 2);
            float r1 = __shfl_xor_sync(FULL, u1, 2);
            float r2 = __shfl_xor_sync(FULL, u2, 2);
            float r3 = __shfl_xor_sync(FULL, u3, 2);
            bool hi2 = (lane & 2) != 0;
            float w0 = hi2 ? (u2 + r2) : (u0 + r0);
            float w1 = hi2 ? (u3 + r3) : (u1 + r1);
            float q0 = __shfl_xor_sync(FULL, w0, 1);
            float q1 = __shfl_xor_sync(FULL, w1, 1);
            z = (lane & 1) ? (w1 + q1) : (w0 + q0);
            z += __shfl_xor_sync(FULL, z, 8);
            z += __shfl_xor_sync(FULL, z, 16);
        }

        // ---- gather the warp's 8 col sums into every lane, publish from 0-7
        {
            float g0 = __shfl_sync(FULL, z, 0, 8);
            float g1 = __shfl_sync(FULL, z, 1, 8);
            float g2 = __shfl_sync(FULL, z, 2, 8);
            float g3 = __shfl_sync(FULL, z, 3, 8);
            float g4 = __shfl_sync(FULL, z, 4, 8);
            float g5 = __shfl_sync(FULL, z, 5, 8);
            float g6 = __shfl_sync(FULL, z, 6, 8);
            float g7 = __shfl_sync(FULL, z, 7, 8);
            if (lane < 8) {
                unsigned ad = rem_data + (unsigned)slot * 2048u;
                st_async_b64(ad,       pack2(g0, g1), mb_r);
                st_async_b64(ad + 8u,  pack2(g2, g3), mb_r);
                st_async_b64(ad + 16u, pack2(g4, g5), mb_r);
                st_async_b64(ad + 24u, pack2(g6, g7), mb_r);
            }
        }

        // ---- HW wait: expect_tx arrive + 2048 tx bytes (64 warp strips)
        mbar_wait_parity(mb_l, (unsigned)((it >> 1) & 1));

        // ---- reduce 16 conflict-free LDS (all col lane&7) + xor{8,16}
        {
            const float* rv = &recv[slot][0];
            float v[16];
#pragma unroll
            for (int k = 0; k < 16; k++) v[k] = rv[lane + (k << 5)];
            float sum = (((v[0] + v[1]) + (v[2] + v[3])) + ((v[4] + v[5]) + (v[6] + v[7])))
                      + (((v[8] + v[9]) + (v[10] + v[11])) + ((v[12] + v[13]) + (v[14] + v[15])));
            sum += __shfl_xor_sync(FULL, sum, 8);
            sum += __shfl_xor_sync(FULL, sum, 16);
            Tc = Dc * sum;                       // true col sum for col lane&7
        }
        dc = bb_c * rcpf(fmaxf(Tc, 1e-37f));     // d_j = b_j / T_j
        Dc = Dc * dc;
        {
            float d0 = __shfl_sync(FULL, Dc, 0, 8);
            float d1 = __shfl_sync(FULL, Dc, 1, 8);
            float d2 = __shfl_sync(FULL, Dc, 2, 8);
            float d3 = __shfl_sync(FULL, Dc, 3, 8);
            float d4 = __shfl_sync(FULL, Dc, 4, 8);
            float d5 = __shfl_sync(FULL, Dc, 5, 8);
            float d6 = __shfl_sync(FULL, Dc, 6, 8);
            float d7 = __shfl_sync(FULL, Dc, 7, 8);
            Dq[0] = pack2(d0, d1);
            Dq[1] = pack2(d2, d3);
            Dq[2] = pack2(d4, d5);
            Dq[3] = pack2(d6, d7);
        }

        // ---- row rescale (packed dot products; skip on last iter)
        if (it != NITER - 1) {
#pragma unroll
            for (int e = 0; e < RPT; e++) {
                u64 acc = mul2(pp[e][0], Dq[0]);
                acc = fma2(pp[e][1], Dq[1], acc);
                acc = fma2(pp[e][2], Dq[2], acc);
                acc = fma2(pp[e][3], Dq[3], acc);
                float wl, wh; unpack2(wl, wh, acc);
                R[e] = a[e] * rcpf(wl + wh);
            }
        }
    }

    // ---- final: P = p0 * R * D / tot;  tot = sum_j T_j * d_j
    float tg = Tc * dc;
    tg += __shfl_xor_sync(FULL, tg, 1);
    tg += __shfl_xor_sync(FULL, tg, 2);
    tg += __shfl_xor_sync(FULL, tg, 4);
    float inv = 1.0f / (tg + 1e-40f);

    float Dn[8];
    {
        float dl, dh;
        unpack2(dl, dh, Dq[0]); Dn[0] = dl * inv; Dn[1] = dh * inv;
        unpack2(dl, dh, Dq[1]); Dn[2] = dl * inv; Dn[3] = dh * inv;
        unpack2(dl, dh, Dq[2]); Dn[4] = dl * inv; Dn[5] = dh * inv;
        unpack2(dl, dh, Dq[3]); Dn[6] = dl * inv; Dn[7] = dh * inv;
    }

    float4* out4 = (float4*)out;
#pragma unroll
    for (int e = 0; e < RPT; e++) {
        int r = base + e;
        float p0[8];
#pragma unroll
        for (int q = 0; q < 4; q++) unpack2(p0[2*q], p0[2*q+1], pp[e][q]);
        float4 o0, o1;
        o0.x = p0[0] * R[e] * Dn[0];  o0.y = p0[1] * R[e] * Dn[1];
        o0.z = p0[2] * R[e] * Dn[2];  o0.w = p0[3] * R[e] * Dn[3];
        o1.x = p0[4] * R[e] * Dn[4];  o1.y = p0[5] * R[e] * Dn[5];
        o1.z = p0[6] * R[e] * Dn[6];  o1.w = p0[7] * R[e] * Dn[7];
        out4[r * 2]     = o0;
        out4[r * 2 + 1] = o1;
    }

    // keep SMEM (mbar/recv) alive until all peers are done
    asm volatile("barrier.cluster.arrive.aligned;" ::: "memory");
    asm volatile("barrier.cluster.wait.aligned;" ::: "memory");
}

// ---------------------------------------------------------------------------
extern "C" void kernel_launch(void* const* d_in, const int* in_sizes, int n_in,
                              void* d_out, int out_size) {
    const float* theta    = (const float*)d_in[0];
    const float* phi      = (const float*)d_in[1];
    const float* sens_raw = (const float*)d_in[2];
    const float* n_raw    = (const float*)d_in[3];
    float*       out      = (float*)d_out;

    da_pre_kernel<<<1, 256>>>(n_raw, sens_raw);
    da_main_kernel<<<NCTA, NT>>>(theta, phi, sens_raw, n_raw, out);
}

// round 17
// speedup vs baseline: 1.2907x; 1.2907x over previous
#include <cuda_runtime.h>

#define NCTA   8
#define NT     256
#define NWARP  8
#define RPT    4                 // rows per thread: 8*256*4 = 8192
#define NITER  200
#define LROWS  8192

typedef unsigned long long u64;

// err = 2^(-2*bits), bits = {2,3,4,5,6,8,10,12}
__constant__ float c_err[8] = {
    6.25e-2f, 1.5625e-2f, 3.90625e-3f, 9.765625e-4f,
    2.44140625e-4f, 1.52587890625e-5f, 9.5367431640625e-7f, 5.9604644775390625e-8f
};

__device__ float g_sum_n;
__device__ float g_inv_sens;

__device__ __forceinline__ float ex2f(float x) {
    float y; asm("ex2.approx.f32 %0, %1;" : "=f"(y) : "f"(x)); return y;
}
__device__ __forceinline__ float lg2f(float x) {
    float y; asm("lg2.approx.f32 %0, %1;" : "=f"(y) : "f"(x)); return y;
}
__device__ __forceinline__ float rcpf(float x) {
    float y; asm("rcp.approx.f32 %0, %1;" : "=f"(y) : "f"(x)); return y;
}
__device__ __forceinline__ u64 pack2(float lo, float hi) {
    u64 r; asm("mov.b64 %0, {%1, %2};" : "=l"(r) : "f"(lo), "f"(hi)); return r;
}
__device__ __forceinline__ void unpack2(float& lo, float& hi, u64 v) {
    asm("mov.b64 {%0, %1}, %2;" : "=f"(lo), "=f"(hi) : "l"(v));
}
__device__ __forceinline__ u64 fma2(u64 a, u64 b, u64 c) {
    u64 d; asm("fma.rn.f32x2 %0, %1, %2, %3;" : "=l"(d) : "l"(a), "l"(b), "l"(c));
    return d;
}
__device__ __forceinline__ u64 mul2(u64 a, u64 b) {
    u64 d; asm("mul.rn.f32x2 %0, %1, %2;" : "=l"(d) : "l"(a), "l"(b));
    return d;
}
__device__ __forceinline__ unsigned smem_u32(const void* p) {
    unsigned a;
    asm("{ .reg .u64 t; cvta.to.shared.u64 t, %1; cvt.u32.u64 %0, t; }"
        : "=r"(a) : "l"(p));
    return a;
}
__device__ __forceinline__ unsigned mapa_u32(unsigned laddr, unsigned rank) {
    unsigned r;
    asm("mapa.shared::cluster.u32 %0, %1, %2;" : "=r"(r) : "r"(laddr), "r"(rank));
    return r;
}
// remote store whose completion is delivered as a tx-decrement on the target's
// mbarrier -- single cross-SM flight, no separate arrive, no release stall
__device__ __forceinline__ void st_async_b64(unsigned addr, u64 v, unsigned mbar) {
    asm volatile("st.async.shared::cluster.mbarrier::complete_tx::bytes.b64 [%0], %1, [%2];"
                 :: "r"(addr), "l"(v), "r"(mbar) : "memory");
}
__device__ __forceinline__ void mbar_expect_tx(unsigned addr, unsigned bytes) {
    asm volatile("mbarrier.arrive.expect_tx.shared.b64 _, [%0], %1;"
                 :: "r"(addr), "r"(bytes) : "memory");
}
__device__ __forceinline__ void mbar_wait_parity(unsigned addr, unsigned par) {
    asm volatile(
        "{\n\t"
        ".reg .pred P;\n"
        "W%=:\n\t"
        "mbarrier.try_wait.parity.acquire.cta.shared::cta.b64 P, [%0], %1, 0x989680;\n\t"
        "@P bra D%=;\n\t"
        "bra W%=;\n"
        "D%=:\n\t"
        "}"
        :: "r"(addr), "r"(par) : "memory");
}

// ---------------------------------------------------------------------------
// Pre-kernel: global input sums (graph-replay deterministic)
// ---------------------------------------------------------------------------
__global__ void da_pre_kernel(const float* __restrict__ n_raw,
                              const float* __restrict__ sens_raw) {
    __shared__ float s1[8], s2[8];
    int t = threadIdx.x;
    float sn = 0.f, ss = 0.f;
    for (int i = t; i < LROWS; i += 256) { sn += n_raw[i]; ss += sens_raw[i]; }
#pragma unroll
    for (int o = 16; o; o >>= 1) {
        sn += __shfl_xor_sync(0xffffffffu, sn, o);
        ss += __shfl_xor_sync(0xffffffffu, ss, o);
    }
    if ((t & 31) == 0) { s1[t >> 5] = sn; s2[t >> 5] = ss; }
    __syncthreads();
    if (t == 0) {
        float a = 0.f, b = 0.f;
#pragma unroll
        for (int w = 0; w < 8; w++) { a += s1[w]; b += s2[w]; }
        g_sum_n    = a * 1e5f + 1e3f * (float)LROWS;
        g_inv_sens = 1.0f / (b + 1e-12f);
    }
}

// ---------------------------------------------------------------------------
// Main kernel: cluster of 8 CTAs x 256 threads, 4 rows/thread. EXACT recurrence.
// Factorized plan p = p0 * R_i * D_j; d_j = b_j / T_j (rcp.approx).
// Exchange: CTA-aggregated strips via st.async+complete_tx; publish is
// DISTRIBUTED: warp w owns target CTA (w+rank)&7, lanes 0-3 send one b64
// column-pair each (32 messages/CTA/iter, same as R15; no warp-0 gather).
// ---------------------------------------------------------------------------
__global__ void __launch_bounds__(NT, 1) __cluster_dims__(NCTA, 1, 1)
da_main_kernel(const float* __restrict__ theta,
               const float* __restrict__ phi,
               const float* __restrict__ sens_raw,
               const float* __restrict__ n_raw,
               float* __restrict__ out) {
    __shared__ __align__(16) float recv[2][64];       // [slot][src*8 + col]
    __shared__ __align__(16) float sred[2][8][NWARP]; // [slot][col][warp]
    __shared__ __align__(8) u64 mbar[2];

    const int tid  = threadIdx.x;
    const int lane = tid & 31;
    const int warp = tid >> 5;
    const unsigned FULL = 0xffffffffu;
    const float L2E = 1.4426950408889634f;

    unsigned rank;
    asm("mov.u32 %0, %%cluster_ctarank;" : "=r"(rank));

    const unsigned recv_base = smem_u32(&recv[0][0]);
    const unsigned mb_addr0  = smem_u32(&mbar[0]);
    const unsigned mb_addr1  = smem_u32(&mbar[1]);

    if (tid == 0) {
        asm volatile("mbarrier.init.shared.b64 [%0], %1;"
                     :: "r"(mb_addr0), "r"(1u) : "memory");
        asm volatile("mbarrier.init.shared.b64 [%0], %1;"
                     :: "r"(mb_addr1), "r"(1u) : "memory");
    }
    asm volatile("barrier.cluster.arrive.aligned;" ::: "memory");
    asm volatile("barrier.cluster.wait.aligned;" ::: "memory");

    // publish addresses: warp w -> target CTA (w+rank)&7; lanes 0-3 send
    // column-pair k at byte offset 8k of this CTA's strip (rank*32)
    unsigned rem_data = 0, rem_mb0 = 0, rem_mb1 = 0;
    {
        unsigned tgt = ((unsigned)warp + rank) & (NCTA - 1);
        rem_data = mapa_u32(recv_base + rank * 32u, tgt);
        rem_mb0  = mapa_u32(mb_addr0, tgt);
        rem_mb1  = mapa_u32(mb_addr1, tgt);
    }

    // b_j (softmax of phi) for column class c = lane&7
    const int mycol = lane & 7;
    float bb_c;
    {
        float q[8];
#pragma unroll
        for (int j = 0; j < 8; j++) q[j] = phi[j] * L2E;
        float m = fmaxf(fmaxf(fmaxf(q[0], q[1]), fmaxf(q[2], q[3])),
                        fmaxf(fmaxf(q[4], q[5]), fmaxf(q[6], q[7])));
        float s = 0.f;
#pragma unroll
        for (int j = 0; j < 8; j++) s += ex2f(q[j] - m);
        bb_c = ex2f(q[mycol] - m - lg2f(s));
    }

    // per-row constants + p0 (packed row-shifted exponentials) + R = a/S
    const int   base = ((int)rank * NT + tid) * RPT;
    const float inv_sumn = 1.0f / g_sum_n;
    const float inv_sens = g_inv_sens;
    const float SC = 50.0f * L2E;

    float a[RPT], R[RPT];
    u64   pp[RPT][4];                       // packed col pairs (01,23,45,67)
    {
        float4 nv = *(const float4*)(n_raw + base);
        float4 sv = *(const float4*)(sens_raw + base);
        float nn[RPT] = { nv.x, nv.y, nv.z, nv.w };
        float se[RPT] = { sv.x, sv.y, sv.z, sv.w };
        const float4* t4 = (const float4*)theta;
#pragma unroll
        for (int e = 0; e < RPT; e++) {
            float n  = nn[e] * 1e5f + 1e3f;
            a[e]     = n * inv_sumn;
            float cs = n * se[e] * inv_sens;
            int   r  = base + e;
            float4 ta = t4[r * 2], tb = t4[r * 2 + 1];
            float x[8];
            x[0] = (ta.x - cs * c_err[0]) * SC;
            x[1] = (ta.y - cs * c_err[1]) * SC;
            x[2] = (ta.z - cs * c_err[2]) * SC;
            x[3] = (ta.w - cs * c_err[3]) * SC;
            x[4] = (tb.x - cs * c_err[4]) * SC;
            x[5] = (tb.y - cs * c_err[5]) * SC;
            x[6] = (tb.z - cs * c_err[6]) * SC;
            x[7] = (tb.w - cs * c_err[7]) * SC;
            float m = fmaxf(fmaxf(fmaxf(x[0], x[1]), fmaxf(x[2], x[3])),
                            fmaxf(fmaxf(x[4], x[5]), fmaxf(x[6], x[7])));
            float p0[8], S = 0.f;
#pragma unroll
            for (int j = 0; j < 8; j++) { p0[j] = ex2f(x[j] - m); S += p0[j]; }
            R[e] = __fdividef(a[e], S);              // rows of p0*R sum to a
#pragma unroll
            for (int q = 0; q < 4; q++) pp[e][q] = pack2(p0[2*q], p0[2*q+1]);
        }
    }

    u64   Dq[4];
#pragma unroll
    for (int q = 0; q < 4; q++) Dq[q] = pack2(1.f, 1.f);
    float Dc = 1.f, Tc = 1.f, dc = 1.f;

    for (int it = 0; it < NITER; ++it) {
        const int      slot = it & 1;
        const unsigned mb_l = slot ? mb_addr1 : mb_addr0;
        const unsigned mb_r = slot ? rem_mb1 : rem_mb0;

        // ---- re-arm local mbar early (negative tx transients are spec-legal)
        if (tid == 0) mbar_expect_tx(mb_l, 8u * 32u);

        // ---- column partials of p0*R over this thread's 4 rows (packed FMA)
        u64 Rp[RPT];
#pragma unroll
        for (int e = 0; e < RPT; e++) Rp[e] = pack2(R[e], R[e]);
        float c0[8];
#pragma unroll
        for (int q = 0; q < 4; q++) {
            u64 acc = mul2(pp[0][q], Rp[0]);
            acc = fma2(pp[1][q], Rp[1], acc);
            acc = fma2(pp[2][q], Rp[2], acc);
            acc = fma2(pp[3][q], Rp[3], acc);
            unpack2(c0[2*q], c0[2*q+1], acc);
        }

        // ---- butterfly transpose-reduce: lane holds warp col sum for col lane&7
        float z;
        {
            float s0 = __shfl_xor_sync(FULL, c0[0], 4);
            float s1 = __shfl_xor_sync(FULL, c0[1], 4);
            float s2 = __shfl_xor_sync(FULL, c0[2], 4);
            float s3 = __shfl_xor_sync(FULL, c0[3], 4);
            float s4 = __shfl_xor_sync(FULL, c0[4], 4);
            float s5 = __shfl_xor_sync(FULL, c0[5], 4);
            float s6 = __shfl_xor_sync(FULL, c0[6], 4);
            float s7 = __shfl_xor_sync(FULL, c0[7], 4);
            bool hi4 = (lane & 4) != 0;
            float u0 = hi4 ? (c0[4] + s4) : (c0[0] + s0);
            float u1 = hi4 ? (c0[5] + s5) : (c0[1] + s1);
            float u2 = hi4 ? (c0[6] + s6) : (c0[2] + s2);
            float u3 = hi4 ? (c0[7] + s7) : (c0[3] + s3);
            float r0 = __shfl_xor_sync(FULL, u0, 2);
            float r1 = __shfl_xor_sync(FULL, u1, 2);
            float r2 = __shfl_xor_sync(FULL, u2, 2);
            float r3 = __shfl_xor_sync(FULL, u3, 2);
            bool hi2 = (lane & 2) != 0;
            float w0 = hi2 ? (u2 + r2) : (u0 + r0);
            float w1 = hi2 ? (u3 + r3) : (u1 + r1);
            float q0 = __shfl_xor_sync(FULL, w0, 1);
            float q1 = __shfl_xor_sync(FULL, w1, 1);
            z = (lane & 1) ? (w1 + q1) : (w0 + q0);
            z += __shfl_xor_sync(FULL, z, 8);
            z += __shfl_xor_sync(FULL, z, 16);
        }
        if (lane < 8) sred[slot][lane][warp] = z;

        // ---- full CTA barrier, then DISTRIBUTED publish: warp w -> its target
        __syncthreads();
        if (lane < 4) {
            int ca = lane * 2, cb = lane * 2 + 1;
            float4 la = *(const float4*)&sred[slot][ca][0];
            float4 lb = *(const float4*)&sred[slot][ca][4];
            float4 lc = *(const float4*)&sred[slot][cb][0];
            float4 ld = *(const float4*)&sred[slot][cb][4];
            float sa = ((la.x + la.y) + (la.z + la.w)) + ((lb.x + lb.y) + (lb.z + lb.w));
            float sb = ((lc.x + lc.y) + (lc.z + lc.w)) + ((ld.x + ld.y) + (ld.z + ld.w));
            unsigned ad = rem_data + (unsigned)slot * 256u + (unsigned)lane * 8u;
            st_async_b64(ad, pack2(sa, sb), mb_r);
        }

        // ---- HW wait: expect_tx arrive + 256 tx bytes (8 CTA strips)
        mbar_wait_parity(mb_l, (unsigned)((it >> 1) & 1));

        // ---- reduce 8 broadcast LDS (conflict-free) to raw column sum
        {
            const float* rv = &recv[slot][0];
            float v0 = rv[mycol],      v1 = rv[mycol + 8];
            float v2 = rv[mycol + 16], v3 = rv[mycol + 24];
            float v4 = rv[mycol + 32], v5 = rv[mycol + 40];
            float v6 = rv[mycol + 48], v7 = rv[mycol + 56];
            float sum = ((v0 + v1) + (v2 + v3)) + ((v4 + v5) + (v6 + v7));
            Tc = Dc * sum;                       // true col sum for col lane&7
        }
        dc = bb_c * rcpf(fmaxf(Tc, 1e-37f));     // d_j = b_j / T_j
        Dc = Dc * dc;
        {
            float d0 = __shfl_sync(FULL, Dc, 0, 8);
            float d1 = __shfl_sync(FULL, Dc, 1, 8);
            float d2 = __shfl_sync(FULL, Dc, 2, 8);
            float d3 = __shfl_sync(FULL, Dc, 3, 8);
            float d4 = __shfl_sync(FULL, Dc, 4, 8);
            float d5 = __shfl_sync(FULL, Dc, 5, 8);
            float d6 = __shfl_sync(FULL, Dc, 6, 8);
            float d7 = __shfl_sync(FULL, Dc, 7, 8);
            Dq[0] = pack2(d0, d1);
            Dq[1] = pack2(d2, d3);
            Dq[2] = pack2(d4, d5);
            Dq[3] = pack2(d6, d7);
        }

        // ---- row rescale (packed dot products; skip on last iter)
        if (it != NITER - 1) {
#pragma unroll
            for (int e = 0; e < RPT; e++) {
                u64 acc = mul2(pp[e][0], Dq[0]);
                acc = fma2(pp[e][1], Dq[1], acc);
                acc = fma2(pp[e][2], Dq[2], acc);
                acc = fma2(pp[e][3], Dq[3], acc);
                float wl, wh; unpack2(wl, wh, acc);
                R[e] = a[e] * rcpf(wl + wh);
            }
        }
    }

    // ---- final: P = p0 * R * D / tot;  tot = sum_j T_j * d_j
    float tg = Tc * dc;
    tg += __shfl_xor_sync(FULL, tg, 1);
    tg += __shfl_xor_sync(FULL, tg, 2);
    tg += __shfl_xor_sync(FULL, tg, 4);
    float inv = 1.0f / (tg + 1e-40f);

    float Dn[8];
    {
        float dl, dh;
        unpack2(dl, dh, Dq[0]); Dn[0] = dl * inv; Dn[1] = dh * inv;
        unpack2(dl, dh, Dq[1]); Dn[2] = dl * inv; Dn[3] = dh * inv;
        unpack2(dl, dh, Dq[2]); Dn[4] = dl * inv; Dn[5] = dh * inv;
        unpack2(dl, dh, Dq[3]); Dn[6] = dl * inv; Dn[7] = dh * inv;
    }

    float4* out4 = (float4*)out;
#pragma unroll
    for (int e = 0; e < RPT; e++) {
        int r = base + e;
        float p0[8];
#pragma unroll
        for (int q = 0; q < 4; q++) unpack2(p0[2*q], p0[2*q+1], pp[e][q]);
        float4 o0, o1;
        o0.x = p0[0] * R[e] * Dn[0];  o0.y = p0[1] * R[e] * Dn[1];
        o0.z = p0[2] * R[e] * Dn[2];  o0.w = p0[3] * R[e] * Dn[3];
        o1.x = p0[4] * R[e] * Dn[4];  o1.y = p0[5] * R[e] * Dn[5];
        o1.z = p0[6] * R[e] * Dn[6];  o1.w = p0[7] * R[e] * Dn[7];
        out4[r * 2]     = o0;
        out4[r * 2 + 1] = o1;
    }

    // keep SMEM (mbar/recv) alive until all peers are done
    asm volatile("barrier.cluster.arrive.aligned;" ::: "memory");
    asm volatile("barrier.cluster.wait.aligned;" ::: "memory");
}

// ---------------------------------------------------------------------------
extern "C" void kernel_launch(void* const* d_in, const int* in_sizes, int n_in,
                              void* d_out, int out_size) {
    const float* theta    = (const float*)d_in[0];
    const float* phi      = (const float*)d_in[1];
    const float* sens_raw = (const float*)d_in[2];
    const float* n_raw    = (const float*)d_in[3];
    float*       out      = (float*)d_out;

    da_pre_kernel<<<1, 256>>>(n_raw, sens_raw);
    da_main_kernel<<<NCTA, NT>>>(theta, phi, sens_raw, n_raw, out);
}